// round 1
// baseline (speedup 1.0000x reference)
#include <cuda_runtime.h>

#define BATCH    16
#define NTUP     65536
#define DSAMP    8
#define IN_SIZE  4096
#define OUT_SIZE 4096

// y[b*OUT_SIZE + o] = bias[o]
__global__ void hyper_init_kernel(const float* __restrict__ bias,
                                  float* __restrict__ y) {
    int i = blockIdx.x * blockDim.x + threadIdx.x;
    if (i < BATCH * OUT_SIZE) y[i] = bias[i & (OUT_SIZE - 1)];
}

template <int TPT>
__global__ __launch_bounds__(256)
void hyper_main_kernel(const float*  __restrict__ x,
                       const float2* __restrict__ means,
                       const float*  __restrict__ sigmas,
                       const float*  __restrict__ values,
                       const float4* __restrict__ noise,
                       float* __restrict__ y) {
    __shared__ float sx[IN_SIZE];

    const int b = blockIdx.y;
    // stage x[b] (16KB) into shared
    {
        const float4* xb4 = reinterpret_cast<const float4*>(x + b * IN_SIZE);
        float4* sx4 = reinterpret_cast<float4*>(sx);
        #pragma unroll
        for (int i = threadIdx.x; i < IN_SIZE / 4; i += 256)
            sx4[i] = xb4[i];
    }
    __syncthreads();

    float* __restrict__ yb = y + b * OUT_SIZE;
    const int bn0  = b * NTUP;
    const int base = blockIdx.x * (256 * TPT);

    #pragma unroll
    for (int it = 0; it < TPT; it++) {
        const int n  = base + it * 256 + threadIdx.x;   // coalesced across warp
        const int bn = bn0 + n;

        const float2 mu  = means[bn];
        const float  sg  = sigmas[bn];
        const float  val = values[bn];

        // noise[b,n,:,:] = 16 floats = 4x float4
        const float4 nz0 = noise[bn * 4 + 0];
        const float4 nz1 = noise[bn * 4 + 1];
        const float4 nz2 = noise[bn * 4 + 2];
        const float4 nz3 = noise[bn * 4 + 3];

        float nr[16] = { nz0.x, nz0.y, nz0.z, nz0.w,
                         nz1.x, nz1.y, nz1.z, nz1.w,
                         nz2.x, nz2.y, nz2.z, nz2.w,
                         nz3.x, nz3.y, nz3.z, nz3.w };

        // probs: sigma and the (2*pi*s2) denominator cancel in normalization
        float p[DSAMP];
        float psum = 0.0f;
        #pragma unroll
        for (int d = 0; d < DSAMP; d++) {
            const float a = nr[2 * d + 0];
            const float c = nr[2 * d + 1];
            p[d] = __expf(-0.5f * (a * a + c * c));
            psum += p[d];
        }
        const float scale = val / psum;

        #pragma unroll
        for (int d = 0; d < DSAMP; d++) {
            // sample = noise*sigma + mean (diff from mean is noise*sigma)
            const float s0 = fmaf(nr[2 * d + 0], sg, mu.x);
            const float s1 = fmaf(nr[2 * d + 1], sg, mu.y);
            // round-half-even (matches jnp.round), clamp, cast
            float f0 = rintf(s0);
            float f1 = rintf(s1);
            f0 = fminf(fmaxf(f0, 0.0f), (float)(OUT_SIZE - 1));
            f1 = fminf(fmaxf(f1, 0.0f), (float)(IN_SIZE - 1));
            const int oi = (int)f0;
            const int ii = (int)f1;
            const float w = scale * p[d];
            atomicAdd(&yb[oi], w * sx[ii]);   // no return use -> RED.ADD.F32
        }
    }
}

extern "C" void kernel_launch(void* const* d_in, const int* in_sizes, int n_in,
                              void* d_out, int out_size) {
    const float*  x      = (const float*) d_in[0];  // [16, 4096]
    const float2* means  = (const float2*)d_in[1];  // [16, 65536, 2]
    const float*  sigmas = (const float*) d_in[2];  // [16, 65536]
    const float*  values = (const float*) d_in[3];  // [16, 65536]
    const float*  bias   = (const float*) d_in[4];  // [4096]
    const float4* noise  = (const float4*)d_in[5];  // [16, 65536, 8, 2]
    float* y = (float*)d_out;                       // [16, 4096]

    // init output with bias (d_out is poisoned before timing)
    hyper_init_kernel<<<(BATCH * OUT_SIZE + 255) / 256, 256>>>(bias, y);

    constexpr int TPT = 4;                           // tuples per thread
    dim3 grid(NTUP / (256 * TPT), BATCH);            // (64, 16)
    hyper_main_kernel<TPT><<<grid, 256>>>(x, means, sigmas, values, noise, y);
}